// round 13
// baseline (speedup 1.0000x reference)
#include <cuda_runtime.h>
#include <cuda_bf16.h>
#include <stdint.h>

// ---------------- problem-size constants (static scratch sizing) ----------------
#define MAXN 50000
#define MAXE 800000
#define CH1  512
#define KCHMAX 16           // 512 / 32 k-chunks

// ---------------- static device scratch (no allocations allowed) ----------------
__device__ float g_y [(size_t)MAXN * CH1];
__device__ float g_dinv[MAXN];
__device__ int   g_counts[MAXN];
__device__ int   g_rowstart[MAXN + 1];
__device__ int   g_cursor[MAXN];
__device__ int   g_csrc[MAXE];
__device__ int   g_blocksum[256];
__device__ int   g_is64;
// split-bf16 chunked layouts: [row][chunk][32 hi bf16 | 32 lo bf16] (128 B each)
__device__ unsigned char g_hsplit[(size_t)MAXN * KCHMAX * 128];
__device__ unsigned char g_W1s[512 * KCHMAX * 128];
__device__ unsigned char g_Wrs[512 * KCHMAX * 128];
__device__ unsigned char g_Wxs[256 * KCHMAX * 128];

// ---------------- small PTX helpers (sm_80-compatible path only) ----------------
__device__ __forceinline__ uint32_t smem_u32(const void* p) {
    uint32_t a;
    asm("{ .reg .u64 t; cvta.to.shared.u64 t, %1; cvt.u32.u64 %0, t; }" : "=r"(a) : "l"(p));
    return a;
}
__device__ __forceinline__ void ldsm4(uint32_t addr, uint32_t& r0, uint32_t& r1,
                                      uint32_t& r2, uint32_t& r3) {
    asm volatile("ldmatrix.sync.aligned.m8n8.x4.shared.b16 {%0,%1,%2,%3}, [%4];"
                 : "=r"(r0), "=r"(r1), "=r"(r2), "=r"(r3) : "r"(addr));
}
__device__ __forceinline__ void mma16816(float* d, const uint32_t* a, const uint32_t* b) {
    asm volatile(
        "mma.sync.aligned.m16n8k16.row.col.f32.bf16.bf16.f32 "
        "{%0,%1,%2,%3}, {%4,%5,%6,%7}, {%8,%9}, {%0,%1,%2,%3};"
        : "+f"(d[0]), "+f"(d[1]), "+f"(d[2]), "+f"(d[3])
        : "r"(a[0]), "r"(a[1]), "r"(a[2]), "r"(a[3]), "r"(b[0]), "r"(b[1]));
}
__device__ __forceinline__ void cp_async16(uint32_t dst, const void* src, int srcsize) {
    asm volatile("cp.async.cg.shared.global [%0], [%1], 16, %2;"
                 :: "r"(dst), "l"(src), "r"(srcsize) : "memory");
}
#define CP_COMMIT() asm volatile("cp.async.commit_group;" ::: "memory")
#define CP_WAIT(n)  asm volatile("cp.async.wait_group %0;" :: "n"(n) : "memory")

// logical->physical swizzle within a 128B row: XOR 16B-block id with (row&7)
#define SWROW(row, off) (((uint32_t)(row)) * 128u + (((uint32_t)(off)) ^ ((((uint32_t)(row)) & 7u) << 4)))

// pack float4 -> split-bf16 (hi uint2, lo uint2)
__device__ __forceinline__ void pack_split(float4 v, uint2& hv, uint2& lv) {
    __nv_bfloat16 h0 = __float2bfloat16(v.x);
    __nv_bfloat16 h1 = __float2bfloat16(v.y);
    __nv_bfloat16 h2 = __float2bfloat16(v.z);
    __nv_bfloat16 h3 = __float2bfloat16(v.w);
    __nv_bfloat16 l0 = __float2bfloat16(v.x - __bfloat162float(h0));
    __nv_bfloat16 l1 = __float2bfloat16(v.y - __bfloat162float(h1));
    __nv_bfloat16 l2 = __float2bfloat16(v.z - __bfloat162float(h2));
    __nv_bfloat16 l3 = __float2bfloat16(v.w - __bfloat162float(h3));
    hv.x = ((uint32_t)__bfloat16_as_ushort(h1) << 16) | __bfloat16_as_ushort(h0);
    hv.y = ((uint32_t)__bfloat16_as_ushort(h3) << 16) | __bfloat16_as_ushort(h2);
    lv.x = ((uint32_t)__bfloat16_as_ushort(l1) << 16) | __bfloat16_as_ushort(l0);
    lv.y = ((uint32_t)__bfloat16_as_ushort(l3) << 16) | __bfloat16_as_ushort(l2);
}
__device__ __forceinline__ float2 unpack_bf2(uint32_t u) {
    __nv_bfloat16 a = __ushort_as_bfloat16((unsigned short)(u & 0xFFFF));
    __nv_bfloat16 b = __ushort_as_bfloat16((unsigned short)(u >> 16));
    return make_float2(__bfloat162float(a), __bfloat162float(b));
}

// ---------------- edge-index width detection (int64 vs int32) ----------------
__global__ void detect64_kernel(const int* __restrict__ p) {
    __shared__ int ok;
    if (threadIdx.x == 0) ok = 1;
    __syncthreads();
    for (int i = threadIdx.x; i < 1024; i += blockDim.x)
        if (p[2 * i + 1] != 0) ok = 0;
    __syncthreads();
    if (threadIdx.x == 0) g_is64 = ok;
}
__device__ __forceinline__ long long edge_at(const void* ei, long long idx, int is64) {
    return is64 ? ((const long long*)ei)[idx] : (long long)((const int*)ei)[idx];
}

// ---------------- degree / CSR construction (parallel scan, dinv fused) ----------------
__global__ void zero_counts_kernel(int n) {
    int i = blockIdx.x * blockDim.x + threadIdx.x;
    if (i < n) g_counts[i] = 0;
}
__global__ void count_edges_kernel(const void* __restrict__ ei, long long E) {
    long long i = (long long)blockIdx.x * blockDim.x + threadIdx.x;
    if (i >= E) return;
    int d = (int)edge_at(ei, E + i, g_is64);
    atomicAdd(&g_counts[d], 1);
}
__global__ void scanA_kernel(int n) {
    __shared__ int sh[256];
    int t = threadIdx.x;
    int i = blockIdx.x * 256 + t;
    int v = (i < n) ? g_counts[i] : 0;
    int incl = v;
    sh[t] = incl;
    __syncthreads();
    for (int off = 1; off < 256; off <<= 1) {
        int u = (t >= off) ? sh[t - off] : 0;
        __syncthreads();
        incl += u;
        sh[t] = incl;
        __syncthreads();
    }
    if (i < n) g_rowstart[i] = incl - v;       // local exclusive
    if (t == 255) g_blocksum[blockIdx.x] = incl;
}
__global__ void scanB_kernel(int nblocks, int n) {
    __shared__ int sh[256];
    int t = threadIdx.x;
    int v = (t < nblocks) ? g_blocksum[t] : 0;
    int incl = v;
    sh[t] = incl;
    __syncthreads();
    for (int off = 1; off < 256; off <<= 1) {
        int u = (t >= off) ? sh[t - off] : 0;
        __syncthreads();
        incl += u;
        sh[t] = incl;
        __syncthreads();
    }
    if (t < nblocks) g_blocksum[t] = incl - v;  // exclusive
    if (t == 255) g_rowstart[n] = incl;         // grand total
}
__global__ void scanC_kernel(int n) {     // add offsets; init cursor; fused dinv
    int i = blockIdx.x * 256 + threadIdx.x;
    if (i >= n) return;
    int rs = g_rowstart[i] + g_blocksum[blockIdx.x];
    g_rowstart[i] = rs;
    g_cursor[i]   = rs;
    g_dinv[i]     = rsqrtf((float)g_counts[i] + 1.0f);
}
__global__ void scatter_csr_kernel(const void* __restrict__ ei, long long E) {
    long long i = (long long)blockIdx.x * blockDim.x + threadIdx.x;
    if (i >= E) return;
    int is64 = g_is64;
    int s = (int)edge_at(ei, i, is64);
    int d = (int)edge_at(ei, E + i, is64);
    int pos = atomicAdd(&g_cursor[d], 1);
    g_csrc[pos] = s;
}

// ---------------- splitters: fp32 -> chunked split-bf16 layout ----------------
__global__ void split_rows_kernel(const float* __restrict__ src, uint8_t* __restrict__ dst,
                                  int R, int K) {
    int idx = blockIdx.x * blockDim.x + threadIdx.x;   // float4 index
    int n4 = R * (K >> 2);
    if (idx >= n4) return;
    int kq = K >> 2;
    int r = idx / kq;
    int k = (idx - r * kq) << 2;
    float4 v = *(const float4*)(src + (size_t)r * K + k);
    uint2 hv, lv;
    pack_split(v, hv, lv);
    int chunk = k >> 5, i = k & 31;
    size_t base = ((size_t)r * (K >> 5) + chunk) * 128;
    *(uint2*)(dst + base + i * 2)      = hv;
    *(uint2*)(dst + base + 64 + i * 2) = lv;
}
// fused: all three weights -> transposed chunked split layout
__global__ void split_w3_kernel(const float* __restrict__ W1, const float* __restrict__ Wr,
                                const float* __restrict__ Wx,
                                uint8_t* __restrict__ W1s, uint8_t* __restrict__ Wrs,
                                uint8_t* __restrict__ Wxs,
                                int K, int N1, int Nx) {
    int idx = blockIdx.x * blockDim.x + threadIdx.x;
    int kq = K >> 2;
    int sz1 = N1 * kq;
    int szx = Nx * kq;
    const float* W;
    uint8_t* dst;
    int N;
    if (idx < sz1)                 { W = W1; dst = W1s; N = N1; }
    else if (idx < 2 * sz1)        { W = Wr; dst = Wrs; N = N1; idx -= sz1; }
    else if (idx < 2 * sz1 + szx)  { W = Wx; dst = Wxs; N = Nx; idx -= 2 * sz1; }
    else return;
    int n = idx / kq;
    int k = (idx - n * kq) << 2;
    float4 v;
    v.x = W[(size_t)(k + 0) * N + n];
    v.y = W[(size_t)(k + 1) * N + n];
    v.z = W[(size_t)(k + 2) * N + n];
    v.w = W[(size_t)(k + 3) * N + n];
    uint2 hv, lv;
    pack_split(v, hv, lv);
    int chunk = k >> 5, i = k & 31;
    size_t base = ((size_t)n * (K >> 5) + chunk) * 128;
    *(uint2*)(dst + base + i * 2)      = hv;
    *(uint2*)(dst + base + 64 + i * 2) = lv;
}

// ================= split-bf16 (x3) mma.sync GEMM, 128x256 CTA, cp.async 4-stage =================
// C[m,n] = rowscale[m] * sum_k A[m,k]*Bt[n,k]; rowscale==nullptr -> no scaling.
// Register-level software pipeline: B fragments double-buffered across n-tile
// pairs; A fragments double-buffered across k-steps.
#define STAGES 4
#define ASTAGE_B 16384
#define STAGE_BYTES 49152
#define GEMM_SMEM_BYTES (STAGES * STAGE_BYTES)   // 196608

__global__ __launch_bounds__(512)
void gemm_tc_kernel(const uint8_t* __restrict__ Asplit, const uint8_t* __restrict__ Bsplit,
                    float* __restrict__ C, const float* __restrict__ rowscale,
                    int M, int N, int K)
{
    extern __shared__ char smem[];
    const uint32_t sb = smem_u32(smem);
    const int tid  = threadIdx.x;
    const int lane = tid & 31;
    const int wid  = tid >> 5;       // 0..15
    const int wm   = wid & 3;        // 4 M-slices of 32 rows
    const int wn   = wid >> 2;       // 4 N-slices of 64 cols
    const int brow = blockIdx.y * 128;
    const int bcol = blockIdx.x * 256;
    const int NCH  = K >> 5;

    float acc[2][8][4];
#pragma unroll
    for (int mt = 0; mt < 2; mt++)
#pragma unroll
        for (int nt = 0; nt < 8; nt++)
#pragma unroll
            for (int r = 0; r < 4; r++) acc[mt][nt][r] = 0.0f;

    auto issue = [&](int c, int stage) {
#pragma unroll
        for (int j = 0; j < 6; ++j) {
            int g = j * 512 + tid;
            uint32_t sbase = sb + (uint32_t)stage * STAGE_BYTES;
            if (g < 1024) {                  // A tile: 128 rows x 8 segs
                int row = g >> 3, seg = g & 7;
                int grow = brow + row;
                int cl = grow < M ? grow : (M - 1);
                const uint8_t* src = Asplit + ((size_t)cl * NCH + c) * 128 + seg * 16;
                cp_async16(sbase + SWROW(row, seg * 16), src, grow < M ? 16 : 0);
            } else {                         // B tile: 256 rows x 8 segs
                int gb = g - 1024;
                int row = gb >> 3, seg = gb & 7;
                const uint8_t* src = Bsplit + ((size_t)(bcol + row) * NCH + c) * 128 + seg * 16;
                cp_async16(sbase + ASTAGE_B + SWROW(row, seg * 16), src, 16);
            }
        }
    };

#pragma unroll
    for (int s = 0; s < STAGES - 1; ++s) {
        issue(s, s);
        CP_COMMIT();
    }

    const int a_r8  = ((lane >> 3) & 1) * 8 + (lane & 7);
    const int a_q   = (lane >> 4);
    const int b_q   = (lane >> 3) & 1;
    const int b_sel = (lane >> 4);
    const int b_r   = lane & 7;

    // register fragment buffers (software pipeline)
    uint32_t ah[2][2][4], al[2][2][4];   // [kstep][mt][4]
    uint32_t bh[2][2][2], bl[2][2][2];   // [buf][tile-of-pair][2]

    for (int c = 0; c < NCH; ++c) {
        CP_WAIT(STAGES - 2);
        __syncthreads();
        if (c + STAGES - 1 < NCH)
            issue(c + STAGES - 1, (c + STAGES - 1) & (STAGES - 1));
        CP_COMMIT();

        const uint32_t abase = sb + (uint32_t)(c & (STAGES - 1)) * STAGE_BYTES;
        const uint32_t bbase = abase + ASTAGE_B;

        auto loadA = [&](int s) {
#pragma unroll
            for (int mt = 0; mt < 2; ++mt) {
                int row = wm * 32 + mt * 16 + a_r8;
                uint32_t hi_off = (uint32_t)(s * 32 + a_q * 16);
                ldsm4(abase + SWROW(row, hi_off),
                      ah[s][mt][0], ah[s][mt][1], ah[s][mt][2], ah[s][mt][3]);
                ldsm4(abase + SWROW(row, 64 + hi_off),
                      al[s][mt][0], al[s][mt][1], al[s][mt][2], al[s][mt][3]);
            }
        };
        auto loadB = [&](int s, int ntp, int buf) {
            int row = wn * 64 + (ntp * 2 + b_sel) * 8 + b_r;
            uint32_t hi_off = (uint32_t)(s * 32 + b_q * 16);
            ldsm4(bbase + SWROW(row, hi_off),
                  bh[buf][0][0], bh[buf][0][1], bh[buf][1][0], bh[buf][1][1]);
            ldsm4(bbase + SWROW(row, 64 + hi_off),
                  bl[buf][0][0], bl[buf][0][1], bl[buf][1][0], bl[buf][1][1]);
        };

        loadA(0);
        loadB(0, 0, 0);
#pragma unroll
        for (int s = 0; s < 2; ++s) {
#pragma unroll
            for (int ntp = 0; ntp < 4; ++ntp) {
                const int cur = ntp & 1;
                // prefetch next B pair (or next k-step's A + first B) while
                // this pair's 12 MMAs drain
                if (ntp < 3) {
                    loadB(s, ntp + 1, cur ^ 1);
                } else if (s == 0) {
                    loadB(1, 0, cur ^ 1);
                    loadA(1);
                }
#pragma unroll
                for (int mt = 0; mt < 2; ++mt) {
                    mma16816(acc[mt][ntp * 2],     ah[s][mt], bh[cur][0]);
                    mma16816(acc[mt][ntp * 2],     ah[s][mt], bl[cur][0]);
                    mma16816(acc[mt][ntp * 2],     al[s][mt], bh[cur][0]);
                    mma16816(acc[mt][ntp * 2 + 1], ah[s][mt], bh[cur][1]);
                    mma16816(acc[mt][ntp * 2 + 1], ah[s][mt], bl[cur][1]);
                    mma16816(acc[mt][ntp * 2 + 1], al[s][mt], bh[cur][1]);
                }
            }
        }
    }

    // ---- epilogue: optional rowscale, store fp32 ----
#pragma unroll
    for (int mt = 0; mt < 2; ++mt) {
        int row0 = brow + wm * 32 + mt * 16 + (lane >> 2);
        int row1 = row0 + 8;
        float s0 = 1.0f, s1 = 1.0f;
        if (rowscale) {
            s0 = (row0 < M) ? rowscale[row0] : 0.0f;
            s1 = (row1 < M) ? rowscale[row1] : 0.0f;
        }
#pragma unroll
        for (int nt = 0; nt < 8; ++nt) {
            int col = bcol + wn * 64 + nt * 8 + (lane & 3) * 2;
            if (row0 < M) {
                float2 v = make_float2(acc[mt][nt][0] * s0, acc[mt][nt][1] * s0);
                *(float2*)(C + (size_t)row0 * N + col) = v;
            }
            if (row1 < M) {
                float2 v = make_float2(acc[mt][nt][2] * s1, acc[mt][nt][3] * s1);
                *(float2*)(C + (size_t)row1 * N + col) = v;
            }
        }
    }
}

// ---------------- neighborhood aggregation (grid.y = 256-col halves) ----------------
// scale_src=1: y is UNscaled (GEMM1 ran before dinv existed), gather applies
// dinv[src] per row and self term uses dinv[d]; otherwise y is pre-scaled.
__global__ void aggregate_kernel(const float* __restrict__ y,
                                 const float* __restrict__ bias,
                                 float* __restrict__ out,
                                 uint8_t* __restrict__ hsplit,
                                 int C, int do_relu, int use_resid, int scale_src)
{
    int d = blockIdx.x;
    int t = threadIdx.x;          // 0..63
    int col = blockIdx.y * 256 + t * 4;

    float sd = g_dinv[d];
    float4 a0 = *(const float4*)(y + (size_t)d * C + col);   // self loop
    if (scale_src) { a0.x *= sd; a0.y *= sd; a0.z *= sd; a0.w *= sd; }
    float4 a1 = make_float4(0.f, 0.f, 0.f, 0.f);
    float4 a2 = make_float4(0.f, 0.f, 0.f, 0.f);
    float4 a3 = make_float4(0.f, 0.f, 0.f, 0.f);

    int beg = g_rowstart[d];
    int end = g_rowstart[d + 1];
    int j = beg;
    if (scale_src) {
        for (; j + 3 < end; j += 4) {
            int s0 = g_csrc[j], s1 = g_csrc[j + 1], s2 = g_csrc[j + 2], s3 = g_csrc[j + 3];
            float w0 = g_dinv[s0], w1 = g_dinv[s1], w2 = g_dinv[s2], w3 = g_dinv[s3];
            float4 v0 = *(const float4*)(y + (size_t)s0 * C + col);
            float4 v1 = *(const float4*)(y + (size_t)s1 * C + col);
            float4 v2 = *(const float4*)(y + (size_t)s2 * C + col);
            float4 v3 = *(const float4*)(y + (size_t)s3 * C + col);
            a0.x = fmaf(v0.x, w0, a0.x); a0.y = fmaf(v0.y, w0, a0.y);
            a0.z = fmaf(v0.z, w0, a0.z); a0.w = fmaf(v0.w, w0, a0.w);
            a1.x = fmaf(v1.x, w1, a1.x); a1.y = fmaf(v1.y, w1, a1.y);
            a1.z = fmaf(v1.z, w1, a1.z); a1.w = fmaf(v1.w, w1, a1.w);
            a2.x = fmaf(v2.x, w2, a2.x); a2.y = fmaf(v2.y, w2, a2.y);
            a2.z = fmaf(v2.z, w2, a2.z); a2.w = fmaf(v2.w, w2, a2.w);
            a3.x = fmaf(v3.x, w3, a3.x); a3.y = fmaf(v3.y, w3, a3.y);
            a3.z = fmaf(v3.z, w3, a3.z); a3.w = fmaf(v3.w, w3, a3.w);
        }
        for (; j < end; ++j) {
            int s0 = g_csrc[j];
            float w0 = g_dinv[s0];
            float4 v0 = *(const float4*)(y + (size_t)s0 * C + col);
            a0.x = fmaf(v0.x, w0, a0.x); a0.y = fmaf(v0.y, w0, a0.y);
            a0.z = fmaf(v0.z, w0, a0.z); a0.w = fmaf(v0.w, w0, a0.w);
        }
    } else {
        for (; j + 3 < end; j += 4) {
            int s0 = g_csrc[j], s1 = g_csrc[j + 1], s2 = g_csrc[j + 2], s3 = g_csrc[j + 3];
            float4 v0 = *(const float4*)(y + (size_t)s0 * C + col);
            float4 v1 = *(const float4*)(y + (size_t)s1 * C + col);
            float4 v2 = *(const float4*)(y + (size_t)s2 * C + col);
            float4 v3 = *(const float4*)(y + (size_t)s3 * C + col);
            a0.x += v0.x; a0.y += v0.y; a0.z += v0.z; a0.w += v0.w;
            a1.x += v1.x; a1.y += v1.y; a1.z += v1.z; a1.w += v1.w;
            a2.x += v2.x; a2.y += v2.y; a2.z += v2.z; a2.w += v2.w;
            a3.x += v3.x; a3.y += v3.y; a3.z += v3.z; a3.w += v3.w;
        }
        for (; j < end; ++j) {
            int s0 = g_csrc[j];
            float4 v0 = *(const float4*)(y + (size_t)s0 * C + col);
            a0.x += v0.x; a0.y += v0.y; a0.z += v0.z; a0.w += v0.w;
        }
    }
    a0.x += a1.x + a2.x + a3.x;
    a0.y += a1.y + a2.y + a3.y;
    a0.z += a1.z + a2.z + a3.z;
    a0.w += a1.w + a2.w + a3.w;

    float4 bb = *(const float4*)(bias + col);
    float4 r;
    r.x = fmaf(a0.x, sd, bb.x);
    r.y = fmaf(a0.y, sd, bb.y);
    r.z = fmaf(a0.z, sd, bb.z);
    r.w = fmaf(a0.w, sd, bb.w);
    if (do_relu) {
        r.x = fmaxf(r.x, 0.f); r.y = fmaxf(r.y, 0.f);
        r.z = fmaxf(r.z, 0.f); r.w = fmaxf(r.w, 0.f);
    }

    size_t base = ((size_t)d * (C >> 5) + (col >> 5)) * 128;
    int i2 = (col & 31) * 2;

    if (use_resid) {
        uint2 hv = *(const uint2*)(hsplit + base + i2);
        uint2 lv = *(const uint2*)(hsplit + base + 64 + i2);
        float2 h01 = unpack_bf2(hv.x), h23 = unpack_bf2(hv.y);
        float2 l01 = unpack_bf2(lv.x), l23 = unpack_bf2(lv.y);
        r.x += h01.x + l01.x;
        r.y += h01.y + l01.y;
        r.z += h23.x + l23.x;
        r.w += h23.y + l23.y;
    }

    if (out)
        *(float4*)(out + (size_t)d * C + col) = r;

    if (hsplit) {
        uint2 hv, lv;
        pack_split(r, hv, lv);
        *(uint2*)(hsplit + base + i2)      = hv;
        *(uint2*)(hsplit + base + 64 + i2) = lv;
    }
}

// ---------------- launcher ----------------
extern "C" void kernel_launch(void* const* d_in, const int* in_sizes, int n_in,
                              void* d_out, int out_size)
{
    const float* x  = (const float*)d_in[0];
    const void*  ei = d_in[1];
    const float* W1 = (const float*)d_in[2];
    const float* b1 = (const float*)d_in[3];
    const float* Wr = (const float*)d_in[4];
    const float* br = (const float*)d_in[5];
    const float* Wx = (const float*)d_in[6];
    const float* bx = (const float*)d_in[7];

    const int H1n = in_sizes[3];                     // 512
    const int INn = in_sizes[2] / H1n;               // 512
    const int H2n = in_sizes[7];                     // 256
    const int N   = in_sizes[0] / INn;               // 50000
    const long long E = (long long)in_sizes[1] / 2;  // 800000

    float *y, *dinv;
    uint8_t *hsplit, *W1s, *Wrs, *Wxs;
    cudaGetSymbolAddress((void**)&y,      g_y);
    cudaGetSymbolAddress((void**)&dinv,   g_dinv);
    cudaGetSymbolAddress((void**)&hsplit, g_hsplit);
    cudaGetSymbolAddress((void**)&W1s,    g_W1s);
    cudaGetSymbolAddress((void**)&Wrs,    g_Wrs);
    cudaGetSymbolAddress((void**)&Wxs,    g_Wxs);

    cudaFuncSetAttribute(gemm_tc_kernel,
                         cudaFuncAttributeMaxDynamicSharedMemorySize, GEMM_SMEM_BYTES);

    const int mtiles = (N + 127) / 128;
    const int nscanb = (N + 255) / 256;
    const int kq = INn >> 2;
    const int wsplit_total = 2 * H1n * kq + H2n * kq;

    // ---- launches 0..3: splits + detect, then GEMM1 at index 3 (ncu window target) ----
    split_w3_kernel<<<(wsplit_total + 255) / 256, 256>>>(W1, Wr, Wx, W1s, Wrs, Wxs,
                                                         INn, H1n, H2n);
    split_rows_kernel<<<(N * (INn / 4) + 255) / 256, 256>>>(x, hsplit, N, INn);
    detect64_kernel<<<1, 256>>>((const int*)ei);
    {
        // GEMM1 runs BEFORE dinv exists -> no rowscale; layer-1 aggregation
        // applies dinv[src] per gathered row instead (scale_src=1).
        dim3 g(H1n / 256, mtiles);
        gemm_tc_kernel<<<g, 512, GEMM_SMEM_BYTES>>>(hsplit, W1s, y, nullptr, N, H1n, INn);
    }

    // ---- CSR build (independent of GEMM1 output) ----
    zero_counts_kernel<<<nscanb, 256>>>(N);
    count_edges_kernel<<<(int)((E + 255) / 256), 256>>>(ei, E);
    scanA_kernel<<<nscanb, 256>>>(N);
    scanB_kernel<<<1, 256>>>(nscanb, N);
    scanC_kernel<<<nscanb, 256>>>(N);
    scatter_csr_kernel<<<(int)((E + 255) / 256), 256>>>(ei, E);

    // ---- layer 1 aggregation (src-scaled gather) ----
    aggregate_kernel<<<dim3(N, H1n / 256), 64>>>(y, b1, nullptr, hsplit, H1n, 1, 0, 1);

    // --- 4 residual layers: h = relu(gcn(h, Wr, br)) + h   (h lives in hsplit) ---
    for (int l = 0; l < 4; l++) {
        dim3 g(H1n / 256, mtiles);
        gemm_tc_kernel<<<g, 512, GEMM_SMEM_BYTES>>>(hsplit, Wrs, y, dinv, N, H1n, H1n);
        aggregate_kernel<<<dim3(N, H1n / 256), 64>>>(y, br, nullptr, hsplit, H1n, 1, 1, 0);
    }

    // --- output layer: out = gcn(h, Wx, bx) ---
    {
        dim3 g(H2n / 256, mtiles);
        gemm_tc_kernel<<<g, 512, GEMM_SMEM_BYTES>>>(hsplit, Wxs, y, dinv, N, H2n, H1n);
        aggregate_kernel<<<dim3(N, H2n / 256), 64>>>(y, bx, (float*)d_out, nullptr, H2n, 0, 0, 0);
    }
}

// round 14
// speedup vs baseline: 1.1096x; 1.1096x over previous
#include <cuda_runtime.h>
#include <cuda_bf16.h>
#include <stdint.h>

// ---------------- problem-size constants (static scratch sizing) ----------------
#define MAXN 50000
#define MAXE 800000
#define CH1  512
#define KCHMAX 16           // 512 / 32 k-chunks

// ---------------- static device scratch (no allocations allowed) ----------------
__device__ float g_y [(size_t)MAXN * CH1];
__device__ float g_dinv[MAXN];
__device__ int   g_counts[MAXN];
__device__ int   g_rowstart[MAXN + 1];
__device__ int   g_cursor[MAXN];
__device__ int   g_csrc[MAXE];
__device__ int   g_blocksum[256];
__device__ int   g_is64;
// split-bf16 chunked layouts: [row][chunk][32 hi bf16 | 32 lo bf16] (128 B each)
__device__ unsigned char g_hsplit[(size_t)MAXN * KCHMAX * 128];
__device__ unsigned char g_W1s[512 * KCHMAX * 128];
__device__ unsigned char g_Wrs[512 * KCHMAX * 128];
__device__ unsigned char g_Wxs[256 * KCHMAX * 128];

// ---------------- small PTX helpers (sm_80-compatible path only) ----------------
__device__ __forceinline__ uint32_t smem_u32(const void* p) {
    uint32_t a;
    asm("{ .reg .u64 t; cvta.to.shared.u64 t, %1; cvt.u32.u64 %0, t; }" : "=r"(a) : "l"(p));
    return a;
}
__device__ __forceinline__ void ldsm4(uint32_t addr, uint32_t& r0, uint32_t& r1,
                                      uint32_t& r2, uint32_t& r3) {
    asm volatile("ldmatrix.sync.aligned.m8n8.x4.shared.b16 {%0,%1,%2,%3}, [%4];"
                 : "=r"(r0), "=r"(r1), "=r"(r2), "=r"(r3) : "r"(addr));
}
__device__ __forceinline__ void mma16816(float* d, const uint32_t* a, const uint32_t* b) {
    asm volatile(
        "mma.sync.aligned.m16n8k16.row.col.f32.bf16.bf16.f32 "
        "{%0,%1,%2,%3}, {%4,%5,%6,%7}, {%8,%9}, {%0,%1,%2,%3};"
        : "+f"(d[0]), "+f"(d[1]), "+f"(d[2]), "+f"(d[3])
        : "r"(a[0]), "r"(a[1]), "r"(a[2]), "r"(a[3]), "r"(b[0]), "r"(b[1]));
}
__device__ __forceinline__ void cp_async16(uint32_t dst, const void* src, int srcsize) {
    asm volatile("cp.async.cg.shared.global [%0], [%1], 16, %2;"
                 :: "r"(dst), "l"(src), "r"(srcsize) : "memory");
}
#define CP_COMMIT() asm volatile("cp.async.commit_group;" ::: "memory")
#define CP_WAIT(n)  asm volatile("cp.async.wait_group %0;" :: "n"(n) : "memory")

// logical->physical swizzle within a 128B row: XOR 16B-block id with (row&7)
#define SWROW(row, off) (((uint32_t)(row)) * 128u + (((uint32_t)(off)) ^ ((((uint32_t)(row)) & 7u) << 4)))

// pack float4 -> split-bf16 (hi uint2, lo uint2)
__device__ __forceinline__ void pack_split(float4 v, uint2& hv, uint2& lv) {
    __nv_bfloat16 h0 = __float2bfloat16(v.x);
    __nv_bfloat16 h1 = __float2bfloat16(v.y);
    __nv_bfloat16 h2 = __float2bfloat16(v.z);
    __nv_bfloat16 h3 = __float2bfloat16(v.w);
    __nv_bfloat16 l0 = __float2bfloat16(v.x - __bfloat162float(h0));
    __nv_bfloat16 l1 = __float2bfloat16(v.y - __bfloat162float(h1));
    __nv_bfloat16 l2 = __float2bfloat16(v.z - __bfloat162float(h2));
    __nv_bfloat16 l3 = __float2bfloat16(v.w - __bfloat162float(h3));
    hv.x = ((uint32_t)__bfloat16_as_ushort(h1) << 16) | __bfloat16_as_ushort(h0);
    hv.y = ((uint32_t)__bfloat16_as_ushort(h3) << 16) | __bfloat16_as_ushort(h2);
    lv.x = ((uint32_t)__bfloat16_as_ushort(l1) << 16) | __bfloat16_as_ushort(l0);
    lv.y = ((uint32_t)__bfloat16_as_ushort(l3) << 16) | __bfloat16_as_ushort(l2);
}
__device__ __forceinline__ float2 unpack_bf2(uint32_t u) {
    __nv_bfloat16 a = __ushort_as_bfloat16((unsigned short)(u & 0xFFFF));
    __nv_bfloat16 b = __ushort_as_bfloat16((unsigned short)(u >> 16));
    return make_float2(__bfloat162float(a), __bfloat162float(b));
}

// ---------------- edge-index width detection (int64 vs int32) ----------------
__global__ void detect64_kernel(const int* __restrict__ p) {
    __shared__ int ok;
    if (threadIdx.x == 0) ok = 1;
    __syncthreads();
    for (int i = threadIdx.x; i < 1024; i += blockDim.x)
        if (p[2 * i + 1] != 0) ok = 0;
    __syncthreads();
    if (threadIdx.x == 0) g_is64 = ok;
}
__device__ __forceinline__ long long edge_at(const void* ei, long long idx, int is64) {
    return is64 ? ((const long long*)ei)[idx] : (long long)((const int*)ei)[idx];
}

// ---------------- degree / CSR construction (parallel scan, dinv fused) ----------------
__global__ void zero_counts_kernel(int n) {
    int i = blockIdx.x * blockDim.x + threadIdx.x;
    if (i < n) g_counts[i] = 0;
}
__global__ void count_edges_kernel(const void* __restrict__ ei, long long E) {
    long long i = (long long)blockIdx.x * blockDim.x + threadIdx.x;
    if (i >= E) return;
    int d = (int)edge_at(ei, E + i, g_is64);
    atomicAdd(&g_counts[d], 1);
}
__global__ void scanA_kernel(int n) {
    __shared__ int sh[256];
    int t = threadIdx.x;
    int i = blockIdx.x * 256 + t;
    int v = (i < n) ? g_counts[i] : 0;
    int incl = v;
    sh[t] = incl;
    __syncthreads();
    for (int off = 1; off < 256; off <<= 1) {
        int u = (t >= off) ? sh[t - off] : 0;
        __syncthreads();
        incl += u;
        sh[t] = incl;
        __syncthreads();
    }
    if (i < n) g_rowstart[i] = incl - v;       // local exclusive
    if (t == 255) g_blocksum[blockIdx.x] = incl;
}
__global__ void scanB_kernel(int nblocks, int n) {
    __shared__ int sh[256];
    int t = threadIdx.x;
    int v = (t < nblocks) ? g_blocksum[t] : 0;
    int incl = v;
    sh[t] = incl;
    __syncthreads();
    for (int off = 1; off < 256; off <<= 1) {
        int u = (t >= off) ? sh[t - off] : 0;
        __syncthreads();
        incl += u;
        sh[t] = incl;
        __syncthreads();
    }
    if (t < nblocks) g_blocksum[t] = incl - v;  // exclusive
    if (t == 255) g_rowstart[n] = incl;         // grand total
}
__global__ void scanC_kernel(int n) {     // add offsets; init cursor; fused dinv
    int i = blockIdx.x * 256 + threadIdx.x;
    if (i >= n) return;
    int rs = g_rowstart[i] + g_blocksum[blockIdx.x];
    g_rowstart[i] = rs;
    g_cursor[i]   = rs;
    g_dinv[i]     = rsqrtf((float)g_counts[i] + 1.0f);
}
__global__ void scatter_csr_kernel(const void* __restrict__ ei, long long E) {
    long long i = (long long)blockIdx.x * blockDim.x + threadIdx.x;
    if (i >= E) return;
    int is64 = g_is64;
    int s = (int)edge_at(ei, i, is64);
    int d = (int)edge_at(ei, E + i, is64);
    int pos = atomicAdd(&g_cursor[d], 1);
    g_csrc[pos] = s;
}

// ---------------- splitters: fp32 -> chunked split-bf16 layout ----------------
__global__ void split_rows_kernel(const float* __restrict__ src, uint8_t* __restrict__ dst,
                                  int R, int K) {
    int idx = blockIdx.x * blockDim.x + threadIdx.x;   // float4 index
    int n4 = R * (K >> 2);
    if (idx >= n4) return;
    int kq = K >> 2;
    int r = idx / kq;
    int k = (idx - r * kq) << 2;
    float4 v = *(const float4*)(src + (size_t)r * K + k);
    uint2 hv, lv;
    pack_split(v, hv, lv);
    int chunk = k >> 5, i = k & 31;
    size_t base = ((size_t)r * (K >> 5) + chunk) * 128;
    *(uint2*)(dst + base + i * 2)      = hv;
    *(uint2*)(dst + base + 64 + i * 2) = lv;
}
// fused: all three weights -> transposed chunked split layout
__global__ void split_w3_kernel(const float* __restrict__ W1, const float* __restrict__ Wr,
                                const float* __restrict__ Wx,
                                uint8_t* __restrict__ W1s, uint8_t* __restrict__ Wrs,
                                uint8_t* __restrict__ Wxs,
                                int K, int N1, int Nx) {
    int idx = blockIdx.x * blockDim.x + threadIdx.x;
    int kq = K >> 2;
    int sz1 = N1 * kq;
    int szx = Nx * kq;
    const float* W;
    uint8_t* dst;
    int N;
    if (idx < sz1)                 { W = W1; dst = W1s; N = N1; }
    else if (idx < 2 * sz1)        { W = Wr; dst = Wrs; N = N1; idx -= sz1; }
    else if (idx < 2 * sz1 + szx)  { W = Wx; dst = Wxs; N = Nx; idx -= 2 * sz1; }
    else return;
    int n = idx / kq;
    int k = (idx - n * kq) << 2;
    float4 v;
    v.x = W[(size_t)(k + 0) * N + n];
    v.y = W[(size_t)(k + 1) * N + n];
    v.z = W[(size_t)(k + 2) * N + n];
    v.w = W[(size_t)(k + 3) * N + n];
    uint2 hv, lv;
    pack_split(v, hv, lv);
    int chunk = k >> 5, i = k & 31;
    size_t base = ((size_t)n * (K >> 5) + chunk) * 128;
    *(uint2*)(dst + base + i * 2)      = hv;
    *(uint2*)(dst + base + 64 + i * 2) = lv;
}

// ================= split-bf16 (x3) mma.sync GEMM, 128x128 CTA, 2 CTAs/SM =================
// C[m,n] = rowscale[m] * sum_k A[m,k]*Bt[n,k]; rowscale==nullptr -> no scaling.
// 256 threads = 8 warps: wm 0..3 (32-row slices), wn 0..1 (64-col slices).
// 3-stage cp.async pipeline, 32KB/stage = 96KB smem -> 2 CTAs/SM (occ 50%).
#define STAGES 3
#define ASTAGE_B 16384
#define STAGE_BYTES 32768
#define GEMM_SMEM_BYTES (STAGES * STAGE_BYTES)   // 98304

__global__ __launch_bounds__(256, 2)
void gemm_tc_kernel(const uint8_t* __restrict__ Asplit, const uint8_t* __restrict__ Bsplit,
                    float* __restrict__ C, const float* __restrict__ rowscale,
                    int M, int N, int K)
{
    extern __shared__ char smem[];
    const uint32_t sb = smem_u32(smem);
    const int tid  = threadIdx.x;
    const int lane = tid & 31;
    const int wid  = tid >> 5;       // 0..7
    const int wm   = wid & 3;        // 4 M-slices of 32 rows
    const int wn   = wid >> 2;       // 2 N-slices of 64 cols
    const int brow = blockIdx.y * 128;
    const int bcol = blockIdx.x * 128;
    const int NCH  = K >> 5;

    float acc[2][8][4];
#pragma unroll
    for (int mt = 0; mt < 2; mt++)
#pragma unroll
        for (int nt = 0; nt < 8; nt++)
#pragma unroll
            for (int r = 0; r < 4; r++) acc[mt][nt][r] = 0.0f;

    // ---- cp.async tile issue: A 1024 + B 1024 = 2048 x 16B segments over 256 threads ----
    auto issue = [&](int c, int stage) {
#pragma unroll
        for (int j = 0; j < 8; ++j) {
            int g = j * 256 + tid;
            uint32_t sbase = sb + (uint32_t)stage * STAGE_BYTES;
            int tile = g >> 10;              // 0 = A, 1 = B
            int row  = (g >> 3) & 127;
            int seg  = g & 7;
            if (tile == 0) {
                int grow = brow + row;
                int cl = grow < M ? grow : (M - 1);
                const uint8_t* src = Asplit + ((size_t)cl * NCH + c) * 128 + seg * 16;
                cp_async16(sbase + SWROW(row, seg * 16), src, grow < M ? 16 : 0);
            } else {
                const uint8_t* src = Bsplit + ((size_t)(bcol + row) * NCH + c) * 128 + seg * 16;
                cp_async16(sbase + ASTAGE_B + SWROW(row, seg * 16), src, 16);
            }
        }
    };

    // prologue: stages 0..STAGES-2
#pragma unroll
    for (int s = 0; s < STAGES - 1; ++s) {
        issue(s, s);
        CP_COMMIT();
    }

    const int a_r8  = ((lane >> 3) & 1) * 8 + (lane & 7);
    const int a_q   = (lane >> 4);
    const int b_q   = (lane >> 3) & 1;
    const int b_sel = (lane >> 4);
    const int b_r   = lane & 7;

    int stage = 0;                       // stage of chunk c
    int wstage = STAGES - 1;             // stage to write next prefetch into
    for (int c = 0; c < NCH; ++c) {
        CP_WAIT(STAGES - 2);
        __syncthreads();
        if (c + STAGES - 1 < NCH)
            issue(c + STAGES - 1, wstage);
        CP_COMMIT();

        const uint32_t abase = sb + (uint32_t)stage * STAGE_BYTES;
        const uint32_t bbase = abase + ASTAGE_B;
#pragma unroll
        for (int s = 0; s < 2; ++s) {                 // two k16 steps per chunk
            uint32_t ah[2][4], al[2][4];
#pragma unroll
            for (int mt = 0; mt < 2; ++mt) {
                int row = wm * 32 + mt * 16 + a_r8;
                uint32_t hi_off = (uint32_t)(s * 32 + a_q * 16);
                ldsm4(abase + SWROW(row, hi_off),      ah[mt][0], ah[mt][1], ah[mt][2], ah[mt][3]);
                ldsm4(abase + SWROW(row, 64 + hi_off), al[mt][0], al[mt][1], al[mt][2], al[mt][3]);
            }
#pragma unroll
            for (int ntp = 0; ntp < 4; ++ntp) {       // pairs of n-tiles, consumed immediately
                int ntl = ntp * 2 + b_sel;
                int row = wn * 64 + ntl * 8 + b_r;
                uint32_t hi_off = (uint32_t)(s * 32 + b_q * 16);
                uint32_t bh0[2], bh1[2], bl0[2], bl1[2];
                ldsm4(bbase + SWROW(row, hi_off),      bh0[0], bh0[1], bh1[0], bh1[1]);
                ldsm4(bbase + SWROW(row, 64 + hi_off), bl0[0], bl0[1], bl1[0], bl1[1]);
#pragma unroll
                for (int mt = 0; mt < 2; ++mt) {
                    mma16816(acc[mt][ntp * 2],     ah[mt], bh0);
                    mma16816(acc[mt][ntp * 2],     ah[mt], bl0);
                    mma16816(acc[mt][ntp * 2],     al[mt], bh0);
                    mma16816(acc[mt][ntp * 2 + 1], ah[mt], bh1);
                    mma16816(acc[mt][ntp * 2 + 1], ah[mt], bl1);
                    mma16816(acc[mt][ntp * 2 + 1], al[mt], bh1);
                }
            }
        }
        stage  = (stage  + 1 == STAGES) ? 0 : stage  + 1;
        wstage = (wstage + 1 == STAGES) ? 0 : wstage + 1;
    }

    // ---- epilogue: optional rowscale, store fp32 ----
#pragma unroll
    for (int mt = 0; mt < 2; ++mt) {
        int row0 = brow + wm * 32 + mt * 16 + (lane >> 2);
        int row1 = row0 + 8;
        float s0 = 1.0f, s1 = 1.0f;
        if (rowscale) {
            s0 = (row0 < M) ? rowscale[row0] : 0.0f;
            s1 = (row1 < M) ? rowscale[row1] : 0.0f;
        }
#pragma unroll
        for (int nt = 0; nt < 8; ++nt) {
            int col = bcol + wn * 64 + nt * 8 + (lane & 3) * 2;
            if (row0 < M) {
                float2 v = make_float2(acc[mt][nt][0] * s0, acc[mt][nt][1] * s0);
                *(float2*)(C + (size_t)row0 * N + col) = v;
            }
            if (row1 < M) {
                float2 v = make_float2(acc[mt][nt][2] * s1, acc[mt][nt][3] * s1);
                *(float2*)(C + (size_t)row1 * N + col) = v;
            }
        }
    }
}

// ---------------- neighborhood aggregation (grid.y = 256-col halves) ----------------
// scale_src=1: y is UNscaled (GEMM1 ran before dinv existed), gather applies
// dinv[src] per row and self term uses dinv[d]; otherwise y is pre-scaled.
__global__ void aggregate_kernel(const float* __restrict__ y,
                                 const float* __restrict__ bias,
                                 float* __restrict__ out,
                                 uint8_t* __restrict__ hsplit,
                                 int C, int do_relu, int use_resid, int scale_src)
{
    int d = blockIdx.x;
    int t = threadIdx.x;          // 0..63
    int col = blockIdx.y * 256 + t * 4;

    float sd = g_dinv[d];
    float4 a0 = *(const float4*)(y + (size_t)d * C + col);   // self loop
    if (scale_src) { a0.x *= sd; a0.y *= sd; a0.z *= sd; a0.w *= sd; }
    float4 a1 = make_float4(0.f, 0.f, 0.f, 0.f);
    float4 a2 = make_float4(0.f, 0.f, 0.f, 0.f);
    float4 a3 = make_float4(0.f, 0.f, 0.f, 0.f);

    int beg = g_rowstart[d];
    int end = g_rowstart[d + 1];
    int j = beg;
    if (scale_src) {
        for (; j + 3 < end; j += 4) {
            int s0 = g_csrc[j], s1 = g_csrc[j + 1], s2 = g_csrc[j + 2], s3 = g_csrc[j + 3];
            float w0 = g_dinv[s0], w1 = g_dinv[s1], w2 = g_dinv[s2], w3 = g_dinv[s3];
            float4 v0 = *(const float4*)(y + (size_t)s0 * C + col);
            float4 v1 = *(const float4*)(y + (size_t)s1 * C + col);
            float4 v2 = *(const float4*)(y + (size_t)s2 * C + col);
            float4 v3 = *(const float4*)(y + (size_t)s3 * C + col);
            a0.x = fmaf(v0.x, w0, a0.x); a0.y = fmaf(v0.y, w0, a0.y);
            a0.z = fmaf(v0.z, w0, a0.z); a0.w = fmaf(v0.w, w0, a0.w);
            a1.x = fmaf(v1.x, w1, a1.x); a1.y = fmaf(v1.y, w1, a1.y);
            a1.z = fmaf(v1.z, w1, a1.z); a1.w = fmaf(v1.w, w1, a1.w);
            a2.x = fmaf(v2.x, w2, a2.x); a2.y = fmaf(v2.y, w2, a2.y);
            a2.z = fmaf(v2.z, w2, a2.z); a2.w = fmaf(v2.w, w2, a2.w);
            a3.x = fmaf(v3.x, w3, a3.x); a3.y = fmaf(v3.y, w3, a3.y);
            a3.z = fmaf(v3.z, w3, a3.z); a3.w = fmaf(v3.w, w3, a3.w);
        }
        for (; j < end; ++j) {
            int s0 = g_csrc[j];
            float w0 = g_dinv[s0];
            float4 v0 = *(const float4*)(y + (size_t)s0 * C + col);
            a0.x = fmaf(v0.x, w0, a0.x); a0.y = fmaf(v0.y, w0, a0.y);
            a0.z = fmaf(v0.z, w0, a0.z); a0.w = fmaf(v0.w, w0, a0.w);
        }
    } else {
        for (; j + 3 < end; j += 4) {
            int s0 = g_csrc[j], s1 = g_csrc[j + 1], s2 = g_csrc[j + 2], s3 = g_csrc[j + 3];
            float4 v0 = *(const float4*)(y + (size_t)s0 * C + col);
            float4 v1 = *(const float4*)(y + (size_t)s1 * C + col);
            float4 v2 = *(const float4*)(y + (size_t)s2 * C + col);
            float4 v3 = *(const float4*)(y + (size_t)s3 * C + col);
            a0.x += v0.x; a0.y += v0.y; a0.z += v0.z; a0.w += v0.w;
            a1.x += v1.x; a1.y += v1.y; a1.z += v1.z; a1.w += v1.w;
            a2.x += v2.x; a2.y += v2.y; a2.z += v2.z; a2.w += v2.w;
            a3.x += v3.x; a3.y += v3.y; a3.z += v3.z; a3.w += v3.w;
        }
        for (; j < end; ++j) {
            int s0 = g_csrc[j];
            float4 v0 = *(const float4*)(y + (size_t)s0 * C + col);
            a0.x += v0.x; a0.y += v0.y; a0.z += v0.z; a0.w += v0.w;
        }
    }
    a0.x += a1.x + a2.x + a3.x;
    a0.y += a1.y + a2.y + a3.y;
    a0.z += a1.z + a2.z + a3.z;
    a0.w += a1.w + a2.w + a3.w;

    float4 bb = *(const float4*)(bias + col);
    float4 r;
    r.x = fmaf(a0.x, sd, bb.x);
    r.y = fmaf(a0.y, sd, bb.y);
    r.z = fmaf(a0.z, sd, bb.z);
    r.w = fmaf(a0.w, sd, bb.w);
    if (do_relu) {
        r.x = fmaxf(r.x, 0.f); r.y = fmaxf(r.y, 0.f);
        r.z = fmaxf(r.z, 0.f); r.w = fmaxf(r.w, 0.f);
    }

    size_t base = ((size_t)d * (C >> 5) + (col >> 5)) * 128;
    int i2 = (col & 31) * 2;

    if (use_resid) {
        uint2 hv = *(const uint2*)(hsplit + base + i2);
        uint2 lv = *(const uint2*)(hsplit + base + 64 + i2);
        float2 h01 = unpack_bf2(hv.x), h23 = unpack_bf2(hv.y);
        float2 l01 = unpack_bf2(lv.x), l23 = unpack_bf2(lv.y);
        r.x += h01.x + l01.x;
        r.y += h01.y + l01.y;
        r.z += h23.x + l23.x;
        r.w += h23.y + l23.y;
    }

    if (out)
        *(float4*)(out + (size_t)d * C + col) = r;

    if (hsplit) {
        uint2 hv, lv;
        pack_split(r, hv, lv);
        *(uint2*)(hsplit + base + i2)      = hv;
        *(uint2*)(hsplit + base + 64 + i2) = lv;
    }
}

// ---------------- launcher ----------------
extern "C" void kernel_launch(void* const* d_in, const int* in_sizes, int n_in,
                              void* d_out, int out_size)
{
    const float* x  = (const float*)d_in[0];
    const void*  ei = d_in[1];
    const float* W1 = (const float*)d_in[2];
    const float* b1 = (const float*)d_in[3];
    const float* Wr = (const float*)d_in[4];
    const float* br = (const float*)d_in[5];
    const float* Wx = (const float*)d_in[6];
    const float* bx = (const float*)d_in[7];

    const int H1n = in_sizes[3];                     // 512
    const int INn = in_sizes[2] / H1n;               // 512
    const int H2n = in_sizes[7];                     // 256
    const int N   = in_sizes[0] / INn;               // 50000
    const long long E = (long long)in_sizes[1] / 2;  // 800000

    float *y, *dinv;
    uint8_t *hsplit, *W1s, *Wrs, *Wxs;
    cudaGetSymbolAddress((void**)&y,      g_y);
    cudaGetSymbolAddress((void**)&dinv,   g_dinv);
    cudaGetSymbolAddress((void**)&hsplit, g_hsplit);
    cudaGetSymbolAddress((void**)&W1s,    g_W1s);
    cudaGetSymbolAddress((void**)&Wrs,    g_Wrs);
    cudaGetSymbolAddress((void**)&Wxs,    g_Wxs);

    cudaFuncSetAttribute(gemm_tc_kernel,
                         cudaFuncAttributeMaxDynamicSharedMemorySize, GEMM_SMEM_BYTES);

    const int mtiles = (N + 127) / 128;
    const int nscanb = (N + 255) / 256;
    const int kq = INn >> 2;
    const int wsplit_total = 2 * H1n * kq + H2n * kq;

    // ---- launches 0..3: splits + detect, then GEMM1 at index 3 (ncu window target) ----
    split_w3_kernel<<<(wsplit_total + 255) / 256, 256>>>(W1, Wr, Wx, W1s, Wrs, Wxs,
                                                         INn, H1n, H2n);
    split_rows_kernel<<<(N * (INn / 4) + 255) / 256, 256>>>(x, hsplit, N, INn);
    detect64_kernel<<<1, 256>>>((const int*)ei);
    {
        // GEMM1 runs BEFORE dinv exists -> no rowscale; layer-1 aggregation
        // applies dinv[src] per gathered row instead (scale_src=1).
        dim3 g(H1n / 128, mtiles);
        gemm_tc_kernel<<<g, 256, GEMM_SMEM_BYTES>>>(hsplit, W1s, y, nullptr, N, H1n, INn);
    }

    // ---- CSR build (independent of GEMM1 output) ----
    zero_counts_kernel<<<nscanb, 256>>>(N);
    count_edges_kernel<<<(int)((E + 255) / 256), 256>>>(ei, E);
    scanA_kernel<<<nscanb, 256>>>(N);
    scanB_kernel<<<1, 256>>>(nscanb, N);
    scanC_kernel<<<nscanb, 256>>>(N);
    scatter_csr_kernel<<<(int)((E + 255) / 256), 256>>>(ei, E);

    // ---- layer 1 aggregation (src-scaled gather) ----
    aggregate_kernel<<<dim3(N, H1n / 256), 64>>>(y, b1, nullptr, hsplit, H1n, 1, 0, 1);

    // --- 4 residual layers: h = relu(gcn(h, Wr, br)) + h   (h lives in hsplit) ---
    for (int l = 0; l < 4; l++) {
        dim3 g(H1n / 128, mtiles);
        gemm_tc_kernel<<<g, 256, GEMM_SMEM_BYTES>>>(hsplit, Wrs, y, dinv, N, H1n, H1n);
        aggregate_kernel<<<dim3(N, H1n / 256), 64>>>(y, br, nullptr, hsplit, H1n, 1, 1, 0);
    }

    // --- output layer: out = gcn(h, Wx, bx) ---
    {
        dim3 g(H2n / 128, mtiles);
        gemm_tc_kernel<<<g, 256, GEMM_SMEM_BYTES>>>(hsplit, Wxs, y, dinv, N, H2n, H1n);
        aggregate_kernel<<<dim3(N, H2n / 256), 64>>>(y, bx, (float*)d_out, nullptr, H2n, 0, 0, 0);
    }
}